// round 1
// baseline (speedup 1.0000x reference)
#include <cuda_runtime.h>
#include <stdint.h>

// Problem constants
#define BB 16
#define DD 256
#define TT 2048
#define KK 8192
#define NN (BB*TT)            // 32768 tokens
#define OUTQ (BB*DD*TT)       // 8388608 floats of quantized_st
// Output layout assumption: [quantized_st (OUTQ)][loss (1)][idx (NN)]

__device__ float g_enorm[KK];
__device__ float g_rnorm[NN];
__device__ int   g_idx[NN];
__device__ float g_loss;

// ---------------------------------------------------------------------------
// enorm[k] = sum_d emb[k][d]^2  (one warp per code; order sub-ulp irrelevant)
// ---------------------------------------------------------------------------
__global__ void k_enorm(const float* __restrict__ emb) {
    int gw = (blockIdx.x * blockDim.x + threadIdx.x) >> 5;
    int lane = threadIdx.x & 31;
    if (gw >= KK) return;
    const float* row = emb + (size_t)gw * DD;
    float s = 0.f;
    #pragma unroll
    for (int i = 0; i < 8; i++) {
        float v = row[lane + 32 * i];
        s = __fadd_rn(s, __fmul_rn(v, v));
    }
    #pragma unroll
    for (int o = 16; o; o >>= 1) s = __fadd_rn(s, __shfl_down_sync(0xffffffffu, s, o));
    if (lane == 0) g_enorm[gw] = s;
}

// ---------------------------------------------------------------------------
// rnorm[n] = sum_d z[b][d][t]^2, warp-style order (XLA GPU row-reduce pattern):
// lane l accumulates d = l, l+32, ..., then shfl-down tree 16/8/4/2/1.
// ---------------------------------------------------------------------------
__global__ void k_rnorm(const float* __restrict__ z) {
    int n = (blockIdx.x * blockDim.x + threadIdx.x) >> 5;
    int lane = threadIdx.x & 31;
    if (n >= NN) return;
    int b = n >> 11, t = n & (TT - 1);
    const float* zp = z + (size_t)b * DD * TT + t;
    float s = 0.f;
    #pragma unroll
    for (int i = 0; i < 8; i++) {
        float v = zp[(size_t)(lane + 32 * i) * TT];
        s = __fadd_rn(s, __fmul_rn(v, v));
    }
    #pragma unroll
    for (int o = 16; o; o >>= 1) s = __fadd_rn(s, __shfl_down_sync(0xffffffffu, s, o));
    if (lane == 0) g_rnorm[n] = s;
}

__global__ void k_zero() { g_loss = 0.f; }

// ---------------------------------------------------------------------------
// Argmin "GEMM": block tile 64 tokens x 256 codes, Dk=32 slices over D=256.
// 256 threads, each thread: 8 tokens x 8 codes as 8x4 f32x2 accumulators,
// pairing codes (c, c+32) so every LDS is stride-1 conflict-free.
// Inner product via fma.rn.f32x2 (FFMA2) for 2x fp32 throughput.
// Distance reproduces the reference rounding chain exactly:
//   dist = fl( fl(rnorm + enorm) - fl(2 * dot) ), argmin first-index ties.
// ---------------------------------------------------------------------------
#define TM  64
#define TKC 256
#define DK  32

__global__ __launch_bounds__(256, 1) void k_argmin(
    const float* __restrict__ z, const float* __restrict__ emb,
    float* __restrict__ out, int write_idx)
{
    __shared__ float zs[DK][TM];
    __shared__ float es[DK][TKC + 1];

    const int tid = threadIdx.x;
    const int tx = tid & 31;       // code group (lane)
    const int ty = tid >> 5;       // token group (warp)
    const int m0 = blockIdx.x * TM;
    const int b = m0 >> 11, t0 = m0 & (TT - 1);
    const float* zb = z + (size_t)b * DD * TT + t0;

    float bestd[8];
    int   besti[8];
    #pragma unroll
    for (int i = 0; i < 8; i++) { bestd[i] = __int_as_float(0x7f7fffff); besti[i] = 0; }

    float rrow[8];
    #pragma unroll
    for (int i = 0; i < 8; i++) rrow[i] = g_rnorm[m0 + ty + 8 * i];

    for (int kc = 0; kc < KK; kc += TKC) {
        unsigned long long acc[8][4];
        #pragma unroll
        for (int i = 0; i < 8; i++)
            #pragma unroll
            for (int j = 0; j < 4; j++) acc[i][j] = 0ull;   // packed (0.f, 0.f)

        for (int ds = 0; ds < DD; ds += DK) {
            __syncthreads();   // protect previous slice's reads
            // stage z tile [DK][TM]: contiguous 64-float rows, coalesced
            #pragma unroll
            for (int r = 0; r < (DK * TM) / 256; r++) {
                int idx = tid + r * 256;
                zs[idx >> 6][idx & 63] = zb[(size_t)(ds + (idx >> 6)) * TT + (idx & 63)];
            }
            // stage emb tile [DK][TKC]: 32-float segments per code, coalesced,
            // stride-257 rows -> conflict-free stores
            #pragma unroll
            for (int r = 0; r < (DK * TKC) / 256; r++) {
                int idx = tid + r * 256;
                int kk = idx >> 5, dd2 = idx & 31;
                es[dd2][kk] = emb[(size_t)(kc + kk) * DD + ds + dd2];
            }
            __syncthreads();

            #pragma unroll
            for (int dd = 0; dd < DK; dd++) {
                unsigned long long ev[4];
                #pragma unroll
                for (int j = 0; j < 4; j++) {
                    unsigned lo = __float_as_uint(es[dd][tx + 64 * j]);
                    unsigned hi = __float_as_uint(es[dd][tx + 32 + 64 * j]);
                    asm("mov.b64 %0, {%1,%2};" : "=l"(ev[j]) : "r"(lo), "r"(hi));
                }
                #pragma unroll
                for (int i = 0; i < 8; i++) {
                    unsigned zu = __float_as_uint(zs[dd][ty + 8 * i]);  // warp-broadcast
                    unsigned long long zz;
                    asm("mov.b64 %0, {%1,%1};" : "=l"(zz) : "r"(zu));
                    #pragma unroll
                    for (int j = 0; j < 4; j++)
                        asm("fma.rn.f32x2 %0, %1, %2, %0;"
                            : "+l"(acc[i][j]) : "l"(zz), "l"(ev[j]));
                }
            }
        }

        // epilogue: distances + running argmin (k ascending per thread ->
        // strict < keeps the earliest index automatically)
        #pragma unroll
        for (int j = 0; j < 4; j++) {
            int k0 = kc + tx + 64 * j;
            int k1 = k0 + 32;
            float e0 = g_enorm[k0], e1 = g_enorm[k1];
            #pragma unroll
            for (int i = 0; i < 8; i++) {
                unsigned lo, hi;
                asm("mov.b64 {%0,%1}, %2;" : "=r"(lo), "=r"(hi) : "l"(acc[i][j]));
                float d0 = __fsub_rn(__fadd_rn(rrow[i], e0),
                                     __fmul_rn(2.0f, __uint_as_float(lo)));
                float d1 = __fsub_rn(__fadd_rn(rrow[i], e1),
                                     __fmul_rn(2.0f, __uint_as_float(hi)));
                if (d0 < bestd[i]) { bestd[i] = d0; besti[i] = k0; }
                if (d1 < bestd[i]) { bestd[i] = d1; besti[i] = k1; }
            }
        }
    }

    // cross-lane reduction (all 32 code-groups of a token live in one warp);
    // ties -> smaller index, matching jnp.argmin
    #pragma unroll
    for (int i = 0; i < 8; i++) {
        float d = bestd[i]; int kb = besti[i];
        #pragma unroll
        for (int o = 16; o; o >>= 1) {
            float od = __shfl_xor_sync(0xffffffffu, d, o);
            int   ok = __shfl_xor_sync(0xffffffffu, kb, o);
            if (od < d || (od == d && ok < kb)) { d = od; kb = ok; }
        }
        if (tx == 0) {
            int n = m0 + ty + 8 * i;
            g_idx[n] = kb;
            if (write_idx) out[(size_t)OUTQ + 1 + n] = (float)kb;
        }
    }
}

// ---------------------------------------------------------------------------
// Gather quantized output + loss partial sums.
// Block = 32 consecutive tokens x all 256 d. Lanes span t -> z/out coalesced.
// out = fl(z + fl(q - z)) reproduces the straight-through rounding exactly.
// ---------------------------------------------------------------------------
__global__ void k_gather(const float* __restrict__ z, const float* __restrict__ emb,
                         float* __restrict__ out) {
    __shared__ int sk[32];
    __shared__ float red[8];
    int m0 = blockIdx.x * 32;
    int b = m0 >> 11, t0 = m0 & (TT - 1);
    int tid = threadIdx.x;
    if (tid < 32) sk[tid] = g_idx[m0 + tid];
    __syncthreads();
    int tt = tid & 31, dg = tid >> 5;
    size_t base = (size_t)b * DD * TT + t0 + tt;
    const float* erow = emb + (size_t)sk[tt] * DD;
    float s = 0.f;
    #pragma unroll
    for (int l = 0; l < 32; l++) {
        int d = dg * 32 + l;
        float q  = erow[d];
        float zv = z[base + (size_t)d * TT];
        float df = __fsub_rn(q, zv);
        out[base + (size_t)d * TT] = __fadd_rn(zv, df);
        s = __fmaf_rn(df, df, s);
    }
    #pragma unroll
    for (int o = 16; o; o >>= 1) s += __shfl_xor_sync(0xffffffffu, s, o);
    if ((tid & 31) == 0) red[tid >> 5] = s;
    __syncthreads();
    if (tid < 8) {
        s = red[tid];
        #pragma unroll
        for (int o = 4; o; o >>= 1) s += __shfl_xor_sync(0x000000ffu, s, o);
        if (tid == 0) atomicAdd(&g_loss, s);
    }
}

__global__ void k_final(float* __restrict__ out, int write_loss) {
    if (write_loss) {
        float m = g_loss / (float)OUTQ;           // mean((q - z)^2)
        out[OUTQ] = __fmul_rn(1.25f, m);          // q_loss + 0.25 * e_loss
    }
}

// ---------------------------------------------------------------------------
extern "C" void kernel_launch(void* const* d_in, const int* in_sizes, int n_in,
                              void* d_out, int out_size) {
    const float* z   = (const float*)d_in[0];   // [B, D, T]
    const float* emb = (const float*)d_in[1];   // [K, D]
    float* out = (float*)d_out;

    int write_idx  = (out_size >= OUTQ + 1 + NN) ? 1 : 0;
    int write_loss = (out_size >= OUTQ + 1) ? 1 : 0;

    k_enorm <<<KK / 8, 256>>>(emb);
    k_rnorm <<<NN / 8, 256>>>(z);
    k_zero  <<<1, 1>>>();
    k_argmin<<<NN / TM, 256>>>(z, emb, out, write_idx);
    k_gather<<<NN / 32, 256>>>(z, emb, out);
    k_final <<<1, 1>>>(out, write_loss);
}